// round 4
// baseline (speedup 1.0000x reference)
#include <cuda_runtime.h>
#include <cuda_fp16.h>
#include <cstdint>

// ---------------- problem constants ----------------
#define B_ROWS 16384
#define D_FEAT 256
#define H_HID  64
#define O_OUT  256
#define GRID_CTAS 128

// ---------------- device scratch (static, allocation-free) ----------------
__device__ __half g_u[(size_t)B_ROWS * D_FEAT];      // 8.4 MB fp16 u
__device__ __half g_wc[(size_t)O_OUT * D_FEAT];      // Wc fp16
__device__ float  g_knot[D_FEAT * 64];
__device__ float  g_slope[D_FEAT * 65];
__device__ float  g_inter[D_FEAT * 65];
__device__ unsigned int g_bar = 0;                   // monotonic grid barrier

__device__ __forceinline__ uint32_t smem_u32(const void* p) {
    uint32_t a;
    asm("{ .reg .u64 t; cvta.to.shared.u64 t, %1; cvt.u32.u64 %0, t; }"
        : "=r"(a) : "l"(p));
    return a;
}

// grid-wide barrier: monotonic counter, replay-safe (no reset needed).
__device__ __forceinline__ void grid_sync() {
    __syncthreads();
    if (threadIdx.x == 0) {
        __threadfence();
        unsigned int old = atomicAdd(&g_bar, 1u);
        unsigned int target = (old / GRID_CTAS + 1u) * GRID_CTAS;
        while (*(volatile unsigned int*)&g_bar < target) { }
        __threadfence();
    }
    __syncthreads();
}

// ---------------- GEMM building blocks ----------------
#define CH      64
#define CH_PAD  72
#define A_ST_H  (128 * CH_PAD)   // 9216 halfs / stage
#define B_ST_H  (256 * CH_PAD)   // 18432 halfs / stage
#define FUSED_SMEM_BYTES ((A_ST_H + B_ST_H) * 2 * 2)   // 110592

__device__ __forceinline__ void cp16(uint32_t dst, const void* src) {
    asm volatile("cp.async.cg.shared.global [%0], [%1], 16;"
                 :: "r"(dst), "l"(src));
}
#define CP_COMMIT() asm volatile("cp.async.commit_group;" ::: "memory")
#define CP_WAIT(n)  asm volatile("cp.async.wait_group %0;" :: "n"(n) : "memory")

__device__ __forceinline__ void ldsm_x4(uint32_t* r, uint32_t addr) {
    asm volatile("ldmatrix.sync.aligned.m8n8.x4.shared.b16 {%0,%1,%2,%3}, [%4];"
                 : "=r"(r[0]), "=r"(r[1]), "=r"(r[2]), "=r"(r[3]) : "r"(addr));
}
__device__ __forceinline__ void ldsm_x2(uint32_t* r, uint32_t addr) {
    asm volatile("ldmatrix.sync.aligned.m8n8.x2.shared.b16 {%0,%1}, [%2];"
                 : "=r"(r[0]), "=r"(r[1]) : "r"(addr));
}
__device__ __forceinline__ void mma_16816(float* c, const uint32_t* a,
                                          const uint32_t* b) {
    asm volatile(
        "mma.sync.aligned.m16n8k16.row.col.f32.f16.f16.f32 "
        "{%0,%1,%2,%3}, {%4,%5,%6,%7}, {%8,%9}, {%0,%1,%2,%3};"
        : "+f"(c[0]), "+f"(c[1]), "+f"(c[2]), "+f"(c[3])
        : "r"(a[0]), "r"(a[1]), "r"(a[2]), "r"(a[3]), "r"(b[0]), "r"(b[1]));
}

// =====================================================================
// Fused persistent kernel: 128 CTAs x 512 threads, 1 CTA/SM.
// =====================================================================
__global__ __launch_bounds__(512, 1)
void fused_kernel(const float* __restrict__ x,
                  const float* __restrict__ W1,
                  const float* __restrict__ b1,
                  const float* __restrict__ W2,
                  const float* __restrict__ b2,
                  const float* __restrict__ Wc,
                  const float* __restrict__ bc,
                  float* __restrict__ out)
{
    extern __shared__ char smem_raw[];
    const int tid = threadIdx.x;
    const int wid = tid >> 5;
    const int lid = tid & 31;
    const int bid = blockIdx.x;

    // ============== PHASE 0: PWL tables + Wc convert ==============
    if (bid < 16) {
        // 16 warps/block, warp-per-feature: d = bid*16 + wid
        float* s_t   = reinterpret_cast<float*>(smem_raw) + wid * 384;
        float* s_kt  = s_t + 64;
        float* s_kds = s_t + 128;
        float* s_kdi = s_t + 192;
        // scratch for delta arrays (pre-sort) in registers + smem:
        float* s_ds  = s_t + 256;
        float* s_di  = s_t + 320;

        const int d = bid * 16 + wid;

        float t[2], ds[2], di[2];
        float bs = 0.0f, bi = 0.0f;
        #pragma unroll
        for (int i = 0; i < 2; i++) {
            const int h  = lid + i * 32;
            const float w1 = W1[d * H_HID + h];
            const float bb = b1[d * H_HID + h];
            const float w2 = W2[d * H_HID + h];
            if (w1 != 0.0f) {
                t[i]  = -bb / w1;
                ds[i] = fabsf(w1) * w2;
                di[i] = (w1 > 0.0f) ? (w2 * bb) : (-w2 * bb);
                if (w1 < 0.0f) { bs += w1 * w2; bi += w2 * bb; }
            } else {
                t[i]  = __int_as_float(0x7f800000);
                ds[i] = 0.0f;
                di[i] = 0.0f;
                bi   += w2 * fmaxf(bb, 0.0f);
            }
            s_t[h]  = t[i];
            s_ds[h] = ds[i];
            s_di[h] = di[i];
        }
        #pragma unroll
        for (int off = 16; off >= 1; off >>= 1) {
            bs += __shfl_xor_sync(0xffffffffu, bs, off);
            bi += __shfl_xor_sync(0xffffffffu, bi, off);
        }
        bi += b2[d];

        __syncwarp();
        int r0 = 0, r1 = 0;
        const float t0 = t[0], t1 = t[1];
        #pragma unroll 16
        for (int j = 0; j < 64; j++) {
            float tj = s_t[j];
            r0 += (tj < t0) || (tj == t0 && j < lid);
            r1 += (tj < t1) || (tj == t1 && j < lid + 32);
        }
        s_kt[r0]  = t0;  s_kds[r0] = ds[0]; s_kdi[r0] = di[0];
        s_kt[r1]  = t1;  s_kds[r1] = ds[1]; s_kdi[r1] = di[1];
        __syncwarp();

        const float v0s = s_kds[2 * lid],     v1s = s_kds[2 * lid + 1];
        const float v0i = s_kdi[2 * lid],     v1i = s_kdi[2 * lid + 1];
        float incs = v0s + v1s, inci = v0i + v1i;
        const float ps = incs, pi = inci;
        #pragma unroll
        for (int off = 1; off < 32; off <<= 1) {
            float as_ = __shfl_up_sync(0xffffffffu, incs, off);
            float ai_ = __shfl_up_sync(0xffffffffu, inci, off);
            if (lid >= off) { incs += as_; inci += ai_; }
        }
        const float exs = incs - ps, exi = inci - pi;

        if (lid == 0) {
            g_slope[d * 65] = bs;
            g_inter[d * 65] = bi;
        }
        g_slope[d * 65 + 2 * lid + 1] = bs + exs + v0s;
        g_inter[d * 65 + 2 * lid + 1] = bi + exi + v0i;
        g_slope[d * 65 + 2 * lid + 2] = bs + incs;
        g_inter[d * 65 + 2 * lid + 2] = bi + inci;
        g_knot[d * 64 + 2 * lid]     = s_kt[2 * lid];
        g_knot[d * 64 + 2 * lid + 1] = s_kt[2 * lid + 1];
    } else if (bid >= 32 && bid < 64) {
        // Wc convert: 32 blocks x 512 threads = 16384 float4
        const float4* W4 = reinterpret_cast<const float4*>(Wc);
        int idx = (bid - 32) * 512 + tid;
        float4 f = W4[idx];
        __half2 h0 = __float22half2_rn(make_float2(f.x, f.y));
        __half2 h1 = __float22half2_rn(make_float2(f.z, f.w));
        uint2 pk;
        pk.x = *reinterpret_cast<uint32_t*>(&h0);
        pk.y = *reinterpret_cast<uint32_t*>(&h1);
        *reinterpret_cast<uint2*>(&g_wc[idx * 4]) = pk;
    }

    grid_sync();

    // ============== PHASE 1: eval u ==============
    {
        float* skt  = reinterpret_cast<float*>(smem_raw);          // 32*65
        float* ssl  = skt + 32 * 65;
        float* sin_ = ssl + 32 * 65;

        const int dgroup = bid & 7;
        const int d0 = dgroup * 32;
        const int rowbase = (bid >> 3) * 1024;

        for (int i = tid; i < 32 * 64; i += 512) {
            int dd = i >> 6, j = i & 63;
            skt[dd * 65 + j] = g_knot[(d0 + dd) * 64 + j];
        }
        for (int i = tid; i < 32 * 65; i += 512) {
            int dd = i / 65, k = i % 65;
            ssl[dd * 65 + k]  = g_slope[(d0 + dd) * 65 + k];
            sin_[dd * 65 + k] = g_inter[(d0 + dd) * 65 + k];
        }
        __syncthreads();

        const int dd = tid & 31;
        const int bl = tid >> 5;          // 0..15
        const int d  = d0 + dd;
        const float* kt = &skt[dd * 65];

        #pragma unroll 4
        for (int r = 0; r < 64; r++) {
            int b = rowbase + r * 16 + bl;
            float xv = __ldg(&x[(size_t)b * D_FEAT + d]);
            int lo = 0;
            #pragma unroll
            for (int s = 64; s >= 1; s >>= 1) {
                if (lo + s <= 64) {
                    float tv = kt[lo + s - 1];
                    if (tv < xv) lo += s;
                }
            }
            float u = fmaf(ssl[dd * 65 + lo], xv, sin_[dd * 65 + lo]);
            g_u[(size_t)b * D_FEAT + d] = __float2half(u);
        }
        __syncthreads();   // smem reuse safety before phase 2
    }

    grid_sync();

    // ============== PHASE 2: GEMM out = u @ Wc^T + bc ==============
    {
        __half* As = reinterpret_cast<__half*>(smem_raw);      // [2][128][CH_PAD]
        __half* Bs = As + 2 * A_ST_H;                          // [2][256][CH_PAD]

        const int m0 = bid * 128;
        const uint32_t as_u32 = smem_u32(As);
        const uint32_t bs_u32 = smem_u32(Bs);
        const __half* Asrc = g_u + (size_t)m0 * D_FEAT;

        // chunk issue lambda-style macro
        #define ISSUE_CHUNK(c, st) do {                                        \
            _Pragma("unroll")                                                  \
            for (int i = 0; i < 2; i++) {                                      \
                int idx = tid + i * 512;                                       \
                int row = idx >> 3, k8 = idx & 7;                              \
                cp16(as_u32 + (uint32_t)(((st) * A_ST_H + row * CH_PAD + k8 * 8) * 2), \
                     Asrc + row * D_FEAT + (c) * CH + k8 * 8);                 \
            }                                                                  \
            _Pragma("unroll")                                                  \
            for (int i = 0; i < 4; i++) {                                      \
                int idx = tid + i * 512;                                       \
                int row = idx >> 3, k8 = idx & 7;                              \
                cp16(bs_u32 + (uint32_t)(((st) * B_ST_H + row * CH_PAD + k8 * 8) * 2), \
                     g_wc + row * D_FEAT + (c) * CH + k8 * 8);                 \
            }                                                                  \
        } while (0)

        ISSUE_CHUNK(0, 0); CP_COMMIT();
        ISSUE_CHUNK(1, 1); CP_COMMIT();

        const int warp_m = wid >> 2;   // 0..3
        const int warp_n = wid & 3;    // 0..3

        const int a_row = warp_m * 32 + (lid & 15);
        const uint32_t a_lane = as_u32
            + (uint32_t)((a_row * CH_PAD + ((lid >> 4) << 3)) * 2);
        const int b_row = warp_n * 64 + (lid & 7);
        const uint32_t b_lane = bs_u32
            + (uint32_t)((b_row * CH_PAD + (((lid >> 3) & 1) << 3)) * 2);

        float acc[2][8][4];
        #pragma unroll
        for (int i = 0; i < 2; i++)
            #pragma unroll
            for (int j = 0; j < 8; j++)
                #pragma unroll
                for (int q = 0; q < 4; q++) acc[i][j][q] = 0.0f;

        #pragma unroll
        for (int c = 0; c < 4; c++) {
            if (c < 3) { CP_WAIT(1); } else { CP_WAIT(0); }
            __syncthreads();

            const int st = c & 1;
            const uint32_t a_st = a_lane + (uint32_t)(st * A_ST_H * 2);
            const uint32_t b_st = b_lane + (uint32_t)(st * B_ST_H * 2);

            #pragma unroll
            for (int ks = 0; ks < 4; ks++) {
                const uint32_t kb = (uint32_t)(ks * 32);
                uint32_t afr[2][4];
                #pragma unroll
                for (int tm = 0; tm < 2; tm++)
                    ldsm_x4(afr[tm], a_st + (uint32_t)(tm * 16 * CH_PAD * 2) + kb);
                uint32_t bfr[8][2];
                #pragma unroll
                for (int tn = 0; tn < 8; tn++)
                    ldsm_x2(bfr[tn], b_st + (uint32_t)(tn * 8 * CH_PAD * 2) + kb);
                #pragma unroll
                for (int tm = 0; tm < 2; tm++)
                    #pragma unroll
                    for (int tn = 0; tn < 8; tn++)
                        mma_16816(acc[tm][tn], afr[tm], bfr[tn]);
            }

            __syncthreads();
            if (c < 2) {
                if (c == 0) { ISSUE_CHUNK(2, 0); }
                else        { ISSUE_CHUNK(3, 1); }
                CP_COMMIT();
            }
        }

        const int qr = lid >> 2;
        const int qc = (lid & 3) * 2;
        #pragma unroll
        for (int tn = 0; tn < 8; tn++) {
            const int cb = warp_n * 64 + tn * 8 + qc;
            const float2 bcv = *reinterpret_cast<const float2*>(bc + cb);
            #pragma unroll
            for (int tm = 0; tm < 2; tm++) {
                const int r = m0 + warp_m * 32 + tm * 16 + qr;
                float2 v0, v1;
                v0.x = acc[tm][tn][0] + bcv.x;
                v0.y = acc[tm][tn][1] + bcv.y;
                v1.x = acc[tm][tn][2] + bcv.x;
                v1.y = acc[tm][tn][3] + bcv.y;
                *reinterpret_cast<float2*>(out + (size_t)r * O_OUT + cb) = v0;
                *reinterpret_cast<float2*>(out + (size_t)(r + 8) * O_OUT + cb) = v1;
            }
        }
        #undef ISSUE_CHUNK
    }
}

// =====================================================================
// launch
// =====================================================================
extern "C" void kernel_launch(void* const* d_in, const int* in_sizes, int n_in,
                              void* d_out, int out_size)
{
    const float* x  = (const float*)d_in[0];
    const float* W1 = (const float*)d_in[1];
    const float* b1 = (const float*)d_in[2];
    const float* W2 = (const float*)d_in[3];
    const float* b2 = (const float*)d_in[4];
    const float* Wc = (const float*)d_in[5];
    const float* bc = (const float*)d_in[6];
    float* out = (float*)d_out;

    fused_kernel<<<GRID_CTAS, 512, FUSED_SMEM_BYTES>>>(
        x, W1, b1, W2, b2, Wc, bc, out);
}

namespace {
struct AttrInit {
    AttrInit() {
        cudaFuncSetAttribute(fused_kernel,
                             cudaFuncAttributeMaxDynamicSharedMemorySize,
                             FUSED_SMEM_BYTES);
    }
} g_attr_init;
}